// round 11
// baseline (speedup 1.0000x reference)
#include <cuda_runtime.h>
#include <cstdint>

#define Bn    8
#define Nn    8192
#define Cn    91
#define CAPc  163840          // >= max kept candidates per image (19/proposal)
#define NB    9216            // histogram bins over score float bits >> 12
#define BASE_BIN 251084       // bits(0.05f) >> 12
#define SEL_CAP 1024
#define TPB   1024
#define DETS  100
#define CLIPV 4.135166556742356f   // log(1000/16)
#define FULLM 0xffffffffu

// ------------------------------------------------------------------
// static device scratch (zero-initialized at load; kernels restore the
// zeros they consume -> graph-replay deterministic)
// ------------------------------------------------------------------
__device__ unsigned long long g_keys  [Bn][CAPc];
__device__ unsigned long long g_sorted[Bn][CAPc];   // descending-bin order
__device__ int                g_cnt   [Bn];
__device__ int                g_hist  [Bn][NB];
__device__ int                g_sfx   [Bn][NB];     // suffix counts (>= bin)
__device__ int                g_cursor[Bn][NB];     // scatter cursors (bases)

__device__ __forceinline__ void stf(float* o, int i, float v, int n) {
    if (i < n) o[i] = v;
}

// reference-rounding IoU on offset coordinates; returns (iou > 0.5)
__device__ __forceinline__ bool iou_sup(float4 A, float4 Bx, float off) {
    float ax1 = A.x + off, ay1 = A.y + off, ax2 = A.z + off, ay2 = A.w + off;
    float bx1 = Bx.x + off, by1 = Bx.y + off, bx2 = Bx.z + off, by2 = Bx.w + off;
    float ltx = fmaxf(ax1, bx1), lty = fmaxf(ay1, by1);
    float rbx = fminf(ax2, bx2), rby = fminf(ay2, by2);
    float ww = fmaxf(rbx - ltx, 0.f), hh = fmaxf(rby - lty, 0.f);
    float inter = ww * hh;
    float a1 = (ax2 - ax1) * (ay2 - ay1);
    float a2 = (bx2 - bx1) * (by2 - by1);
    float iou = __fdiv_rn(inter, a1 + a2 - inter + 1e-9f);
    return iou > 0.5f;
}

// byte-identical box decode for candidate (g, c)
__device__ __forceinline__ float4 decode_box(const float* __restrict__ reg,
                                             const float* __restrict__ props,
                                             int g, int c) {
    float4 p = reinterpret_cast<const float4*>(props)[g];
    float w  = p.z - p.x;
    float h  = p.w - p.y;
    float cx = p.x + 0.5f * w;
    float cy = p.y + 0.5f * h;
    const float4* Q = reinterpret_cast<const float4*>(reg + (size_t)g * (Cn * 4));
    float4 q = Q[c];
    float dx = __fdiv_rn(q.x, 10.0f);
    float dy = __fdiv_rn(q.y, 10.0f);
    float dw = fminf(__fdiv_rn(q.z, 5.0f), CLIPV);
    float dh = fminf(__fdiv_rn(q.w, 5.0f), CLIPV);
    float pcx = dx * w + cx;
    float pcy = dy * h + cy;
    float pw  = expf(dw) * w;
    float ph  = expf(dh) * h;
    float x1 = fminf(fmaxf(pcx - 0.5f * pw, 0.f), 800.f);
    float y1 = fminf(fmaxf(pcy - 0.5f * ph, 0.f), 800.f);
    float x2 = fminf(fmaxf(pcx + 0.5f * pw, 0.f), 800.f);
    float y2 = fminf(fmaxf(pcy + 0.5f * ph, 0.f), 800.f);
    return make_float4(x1, y1, x2, y2);
}

// ------------------------------------------------------------------
// K1: softmax + prefilter + warp-compacted decode + key append + hist
// ------------------------------------------------------------------
__global__ __launch_bounds__(256) void k_cand(const float* __restrict__ logits,
                                              const float* __restrict__ reg,
                                              const float* __restrict__ props) {
    int g    = blockIdx.x * 8 + (threadIdx.x >> 5);   // proposal 0..65535
    int lane = threadIdx.x & 31;
    int b = g >> 13;
    int n = g & (Nn - 1);

    const float* L = logits + (size_t)g * Cn;
    float l0 = L[lane];
    float l1 = (lane + 32 < Cn) ? L[lane + 32] : -1e30f;
    float l2 = (lane + 64 < Cn) ? L[lane + 64] : -1e30f;

    float mx = fmaxf(l0, fmaxf(l1, l2));
    #pragma unroll
    for (int o = 16; o; o >>= 1) mx = fmaxf(mx, __shfl_xor_sync(FULLM, mx, o));

    float e0 = expf(l0 - mx);
    float e1 = (lane + 32 < Cn) ? expf(l1 - mx) : 0.0f;
    float e2 = (lane + 64 < Cn) ? expf(l2 - mx) : 0.0f;
    float s = e0 + e1 + e2;
    #pragma unroll
    for (int o = 16; o; o >>= 1) s += __shfl_xor_sync(FULLM, s, o);

    // conservative prefilter (margin >> 1ulp; exact test after compaction)
    float pre_t = 0.0497f * s;
    bool ok0 = (lane >= 1) && (e0 > pre_t);   // c = lane (class 0 excluded)
    bool ok1 = (e1 > pre_t);                  // c = lane+32
    bool ok2 = (e2 > pre_t);                  // c = lane+64

    unsigned mA = __ballot_sync(FULLM, ok0);
    unsigned mB = __ballot_sync(FULLM, ok1);
    unsigned mC = __ballot_sync(FULLM, ok2);
    int c0  = __popc(mA);
    int c01 = c0 + __popc(mB);
    int tot = c01 + __popc(mC);
    if (tot == 0) return;                     // warp-uniform

    // compact candidates into lanes [0, tot)
    int src = 0, k = 0;
    if (lane < c0)       { k = 0; src = __fns(mA, 0, lane + 1); }
    else if (lane < c01) { k = 1; src = __fns(mB, 0, lane - c0 + 1); }
    else if (lane < tot) { k = 2; src = __fns(mC, 0, lane - c01 + 1); }
    src &= 31;
    float eA = __shfl_sync(FULLM, e0, src);
    float eB = __shfl_sync(FULLM, e1, src);
    float eC = __shfl_sync(FULLM, e2, src);
    float e  = (k == 2) ? eC : ((k == 1) ? eB : eA);
    int   c  = src + (k << 5);

    bool ok = (lane < tot);
    float sc = __fdiv_rn(e, s);               // exact softmax value
    ok = ok && (sc > 0.05f);

    if (ok) {
        float4 bx = decode_box(reg, props, g, c);
        ok = ((bx.z - bx.x) >= 1.0f) && ((bx.w - bx.y) >= 1.0f);
    }

    unsigned fm = __ballot_sync(FULLM, ok);
    int cnt = __popc(fm);
    if (cnt) {
        int base = 0;
        if (lane == 0) base = atomicAdd(&g_cnt[b], cnt);
        base = __shfl_sync(FULLM, base, 0);
        if (ok) {
            int pos = base + __popc(fm & ((1u << lane) - 1u));
            if (pos < CAPc) {
                unsigned m = (unsigned)(n * 90 + (c - 1));
                unsigned sb = __float_as_uint(sc);
                g_keys[b][pos] = ((unsigned long long)sb << 32) | (0xFFFFFFFFu - m);
                int bin = (int)(sb >> 12) - BASE_BIN;
                bin = max(0, min(bin, NB - 1));
                atomicAdd(&g_hist[b][bin], 1);
            }
        }
    }
}

// ------------------------------------------------------------------
// K2a: per-image suffix sums over the histogram -> sfx + scatter bases;
//      zeroes g_hist for the next replay.
// ------------------------------------------------------------------
__global__ __launch_bounds__(TPB) void k_pref() {
    __shared__ int wtot[32], wexc[32];
    int b = blockIdx.x;
    int t = threadIdx.x;
    int lane = t & 31;
    int warp = t >> 5;

    const int PER = NB / TPB;   // 9
    int lo = t * PER;
    int cnts[PER];
    #pragma unroll
    for (int i = 0; i < PER; i++) {
        cnts[i] = g_hist[b][lo + i];
        g_hist[b][lo + i] = 0;            // restore zero for replay
    }
    int ls = 0;
    #pragma unroll
    for (int i = 0; i < PER; i++) ls += cnts[i];

    int v = ls;
    #pragma unroll
    for (int off = 1; off < 32; off <<= 1) {
        int u = __shfl_down_sync(FULLM, v, off);
        if (lane + off < 32) v += u;
    }
    if (lane == 0) wtot[warp] = v;
    __syncthreads();
    if (t < 32) {
        int x = wtot[t];
        int vv = x;
        #pragma unroll
        for (int off = 1; off < 32; off <<= 1) {
            int u = __shfl_down_sync(FULLM, vv, off);
            if (t + off < 32) vv += u;
        }
        wexc[t] = vv - x;
    }
    __syncthreads();
    int run = wexc[warp] + (v - ls);      // suffix excluding this thread's bins
    for (int i = PER - 1; i >= 0; i--) {
        run += cnts[i];
        g_sfx[b][lo + i]    = run;        // # keys with bin >= (lo+i)
        g_cursor[b][lo + i] = run - cnts[i];  // base offset for this bin
    }
}

// ------------------------------------------------------------------
// K2b: chip-parallel counting-sort scatter into descending-bin order
// ------------------------------------------------------------------
__global__ __launch_bounds__(TPB) void k_scat() {
    int b = blockIdx.y;
    int cnt = min(g_cnt[b], CAPc);
    for (int i = blockIdx.x * TPB + threadIdx.x; i < cnt; i += gridDim.x * TPB) {
        unsigned long long key = g_keys[b][i];
        int bin = (int)((unsigned)(key >> 32) >> 12) - BASE_BIN;
        bin = max(0, min(bin, NB - 1));
        int pos = atomicAdd(&g_cursor[b][bin], 1);
        g_sorted[b][pos] = key;
    }
}

// ------------------------------------------------------------------
// K3 shared memory
// ------------------------------------------------------------------
struct SM {
    float4 sbox[SEL_CAP];               // window boxes (sorted order)
    float4 cls_acc[32][DETS];           // per-warp class accepted scratch
    float4 abox[DETS];                  // global accepted boxes
    unsigned long long skey[SEL_CAP];
    int    slbl[SEL_CAP];
    int    sfx[NB];
    int    cls_rank[SEL_CAP];
    int    cls_list[SEL_CAP];
    int    sflag[SEL_CAP];
    int    cls_cnt[128];
    int    cls_off[96];
    int    albl[DETS];
    int    wsum[32];
    int    s_acc, s_surv;
};

__global__ __launch_bounds__(TPB) void k_nms(const float* __restrict__ reg,
                                             const float* __restrict__ props,
                                             float* __restrict__ out, int out_size) {
    extern __shared__ __align__(16) char smraw[];
    SM* sm = reinterpret_cast<SM*>(smraw);
    int b = blockIdx.x;
    int t = threadIdx.x;
    int lane = t & 31;
    int warp = t >> 5;

    // ---- load suffix counts into smem ----
    for (int i = t; i < NB; i += TPB) sm->sfx[i] = g_sfx[b][i];
    if (t == 0) sm->s_acc = 0;
    __syncthreads();

    int b_hi = NB;
    int off_hi = 0;                       // invariant: off_hi == sfx[b_hi]

    while (sm->s_acc < DETS) {
        if (b_hi == 0 || sm->sfx[0] - off_hi == 0) break;   // nothing left

        // smallest wlo with sfx[wlo] - off_hi <= SEL_CAP (monotone)
        int sl = 0, sh = b_hi;
        while (sl < sh) {
            int mid = (sl + sh) >> 1;
            if (sm->sfx[mid] - off_hi <= SEL_CAP) sh = mid; else sl = mid + 1;
        }
        int wlo = sl;
        int wend;
        if (wlo >= b_hi) {                // single oversize bin: arbitrary 1024
            wlo = b_hi - 1;
            wend = min(sm->sfx[wlo], off_hi + SEL_CAP);
        } else {
            wend = sm->sfx[wlo];
        }
        int nsel = wend - off_hi;

        // gather contiguous window slice (bin-bounded => order-exact)
        if (t < nsel) sm->skey[t] = g_sorted[b][off_hi + t];
        {
            int i = nsel + t;
            if (i < SEL_CAP) sm->skey[i] = 0ULL;
        }

        // next round state (skip clamped remainder, as before)
        b_hi = wlo;
        off_hi = sm->sfx[wlo];
        if (nsel == 0) continue;
        __syncthreads();

        // ---- register+shfl bitonic sort, descending, P=1024 ----
        {
            unsigned long long key = sm->skey[t];
            #pragma unroll
            for (int k2 = 2; k2 <= SEL_CAP; k2 <<= 1) {
                for (int j = k2 >> 1; j > 0; j >>= 1) {
                    unsigned long long partner;
                    if (j >= 32) {
                        __syncthreads();
                        sm->skey[t] = key;
                        __syncthreads();
                        partner = sm->skey[t ^ j];
                    } else {
                        partner = __shfl_xor_sync(FULLM, key, j);
                    }
                    bool desc    = ((t & k2) == 0);
                    bool lowerIx = ((t & j) == 0);
                    bool takeMax = (desc == lowerIx);
                    bool pG      = (partner > key);
                    if (takeMax == pG) key = partner;
                }
            }
            __syncthreads();
            sm->skey[t] = key;
            __syncthreads();
        }

        // ---- decode boxes + labels in sorted order; reset flags/counters --
        if (t < nsel) {
            unsigned m = 0xFFFFFFFFu - (unsigned)sm->skey[t];
            int n = (int)(m / 90u);
            int c = (int)(m % 90u) + 1;
            sm->sbox[t] = decode_box(reg, props, b * Nn + n, c);
            sm->slbl[t] = c;
        }
        sm->sflag[t] = 0;
        if (t < 128) sm->cls_cnt[t] = 0;
        __syncthreads();

        // ---- stable per-class ranks (single warp, 32 chunks) ----
        if (t < 32) {
            for (int k = 0; k < 32; k++) {
                int i = k * 32 + lane;
                int lbl = (i < nsel) ? sm->slbl[i] : (96 + lane);
                unsigned peers = __match_any_sync(FULLM, lbl);
                int leader = __ffs(peers) - 1;
                int rank = __popc(peers & ((1u << lane) - 1u));
                int base = 0;
                if (lane == leader) {
                    base = sm->cls_cnt[lbl];
                    sm->cls_cnt[lbl] = base + __popc(peers);
                }
                base = __shfl_sync(FULLM, base, leader);
                if (i < nsel) sm->cls_rank[i] = base + rank;
            }
        }
        __syncthreads();

        // ---- exclusive offsets over classes 0..95 ----
        if (t < 32) {
            int c0i = t * 3;
            int s0 = sm->cls_cnt[c0i], s1 = sm->cls_cnt[c0i + 1], s2 = sm->cls_cnt[c0i + 2];
            int tt = s0 + s1 + s2;
            int rn = tt;
            #pragma unroll
            for (int off = 1; off < 32; off <<= 1) {
                int u = __shfl_up_sync(FULLM, rn, off);
                if (lane >= off) rn += u;
            }
            int ex = rn - tt;
            sm->cls_off[c0i] = ex;
            sm->cls_off[c0i + 1] = ex + s0;
            sm->cls_off[c0i + 2] = ex + s0 + s1;
        }
        __syncthreads();

        // ---- scatter per-class lists (stable: score order within class) --
        if (t < nsel) sm->cls_list[sm->cls_off[sm->slbl[t]] + sm->cls_rank[t]] = t;
        int acc0 = sm->s_acc;
        int quota = DETS - acc0;
        __syncthreads();

        // ---- per-class greedy: warp w handles classes w+1, w+33, w+65 ----
        #pragma unroll
        for (int jc = 0; jc < 3; jc++) {
            int c = warp + 1 + 32 * jc;
            if (c > 90) continue;
            int cnt = sm->cls_cnt[c];
            if (cnt == 0) continue;
            int off = sm->cls_off[c];
            float offv = (float)c * 801.0f;

            // load prior accepted boxes of this class
            int nacc = 0;
            for (int a0 = 0; a0 < acc0; a0 += 32) {
                int a = a0 + lane;
                bool mth = (a < acc0) && (sm->albl[a] == c);
                unsigned mm = __ballot_sync(FULLM, mth);
                if (mth) sm->cls_acc[warp][nacc + __popc(mm & ((1u << lane) - 1u))] = sm->abox[a];
                nacc += __popc(mm);
            }

            int newacc = 0;
            for (int j = 0; j < cnt; j++) {
                int i = sm->cls_list[off + j];
                float4 bx = sm->sbox[i];
                bool sup = false;
                for (int a = lane; a < nacc; a += 32)
                    sup |= iou_sup(sm->cls_acc[warp][a], bx, offv);
                if (!__any_sync(FULLM, sup)) {
                    if (lane == 0) {
                        sm->sflag[i] = 1;
                        sm->cls_acc[warp][nacc] = bx;
                    }
                    nacc++;
                    newacc++;
                    if (newacc >= quota) break;   // deeper survivors can't be output
                }
            }
        }
        __syncthreads();

        // ---- prefix over survivor flags; output first quota in order ----
        {
            int f = sm->sflag[t];
            int scn = f;
            #pragma unroll
            for (int off = 1; off < 32; off <<= 1) {
                int u = __shfl_up_sync(FULLM, scn, off);
                if (lane >= off) scn += u;
            }
            if (lane == 31) sm->wsum[warp] = scn;
            __syncthreads();
            if (t < 32) {
                int x = sm->wsum[t];
                int s2 = x;
                #pragma unroll
                for (int off = 1; off < 32; off <<= 1) {
                    int u = __shfl_up_sync(FULLM, s2, off);
                    if (t >= off) s2 += u;
                }
                sm->wsum[t] = s2 - x;   // exclusive warp base
            }
            __syncthreads();
            int incl = scn + sm->wsum[warp];
            int r = incl - f;           // exclusive rank
            if (f && (acc0 + r) < DETS) {
                int slot = acc0 + r;
                float4 bx = sm->sbox[t];
                int lbl = sm->slbl[t];
                sm->abox[slot] = bx;
                sm->albl[slot] = lbl;
                float sc = __uint_as_float((unsigned)(sm->skey[t] >> 32));
                stf(out, b * (DETS * 4) + slot * 4 + 0, bx.x, out_size);
                stf(out, b * (DETS * 4) + slot * 4 + 1, bx.y, out_size);
                stf(out, b * (DETS * 4) + slot * 4 + 2, bx.z, out_size);
                stf(out, b * (DETS * 4) + slot * 4 + 3, bx.w, out_size);
                stf(out, Bn * DETS * 4 + b * DETS + slot, sc, out_size);
                stf(out, Bn * DETS * 5 + b * DETS + slot, (float)lbl, out_size);
                stf(out, Bn * DETS * 6 + b * DETS + slot, 1.0f, out_size);
            }
            if (t == TPB - 1) sm->s_surv = incl;
            __syncthreads();
            if (t == 0) sm->s_acc = min(acc0 + sm->s_surv, DETS);
            __syncthreads();
        }
    }

    // ---- zero-fill remaining detection slots ----
    __syncthreads();
    int accF = sm->s_acc;
    for (int a = accF + t; a < DETS; a += TPB) {
        stf(out, b * (DETS * 4) + a * 4 + 0, 0.f, out_size);
        stf(out, b * (DETS * 4) + a * 4 + 1, 0.f, out_size);
        stf(out, b * (DETS * 4) + a * 4 + 2, 0.f, out_size);
        stf(out, b * (DETS * 4) + a * 4 + 3, 0.f, out_size);
        stf(out, Bn * DETS * 4 + b * DETS + a, 0.f, out_size);
        stf(out, Bn * DETS * 5 + b * DETS + a, 0.f, out_size);
        stf(out, Bn * DETS * 6 + b * DETS + a, 0.f, out_size);
    }

    // ---- restore zeros for next graph replay ----
    if (t == 0) g_cnt[b] = 0;
}

// ------------------------------------------------------------------
// launcher
// ------------------------------------------------------------------
extern "C" void kernel_launch(void* const* d_in, const int* in_sizes, int n_in,
                              void* d_out, int out_size) {
    const float* logits = nullptr;
    const float* reg    = nullptr;
    const float* props  = nullptr;
    for (int i = 0; i < n_in; i++) {
        if      (in_sizes[i] == Bn * Nn * Cn)     logits = (const float*)d_in[i];
        else if (in_sizes[i] == Bn * Nn * Cn * 4) reg    = (const float*)d_in[i];
        else if (in_sizes[i] == Bn * Nn * 4)      props  = (const float*)d_in[i];
    }
    if (!logits && n_in > 0) logits = (const float*)d_in[0];
    if (!reg    && n_in > 1) reg    = (const float*)d_in[1];
    if (!props  && n_in > 2) props  = (const float*)d_in[2];

    cudaFuncSetAttribute(k_nms, cudaFuncAttributeMaxDynamicSharedMemorySize,
                         (int)sizeof(SM));

    k_cand<<<(Bn * Nn) / 8, 256>>>(logits, reg, props);
    k_pref<<<Bn, TPB>>>();
    {
        dim3 grid(32, Bn);
        k_scat<<<grid, TPB>>>();
    }
    k_nms<<<Bn, TPB, sizeof(SM)>>>(reg, props, (float*)d_out, out_size);
}

// round 12
// speedup vs baseline: 1.5625x; 1.5625x over previous
#include <cuda_runtime.h>
#include <cstdint>

#define Bn    8
#define Nn    8192
#define Cn    91
#define CAPc  163840          // >= max kept candidates per image
#define NB    9216            // histogram bins over score float bits >> 12
#define BASE_BIN 251084       // bits(0.05f) >> 12
#define SEL_CAP 1024
#define TPB   1024
#define DETS  100
#define CLIPV 4.135166556742356f   // log(1000/16)
#define FULLM 0xffffffffu

// ------------------------------------------------------------------
// static device scratch (zero-initialized at load; k_nms restores the
// zeros it consumed -> graph-replay deterministic)
// ------------------------------------------------------------------
__device__ unsigned long long g_keys[Bn][CAPc];
__device__ int                g_cnt [Bn];

__device__ __forceinline__ void stf(float* o, int i, float v, int n) {
    if (i < n) o[i] = v;
}

// reference-rounding IoU on offset coordinates; returns (iou > 0.5)
__device__ __forceinline__ bool iou_sup(float4 A, float4 Bx, float off) {
    float ax1 = A.x + off, ay1 = A.y + off, ax2 = A.z + off, ay2 = A.w + off;
    float bx1 = Bx.x + off, by1 = Bx.y + off, bx2 = Bx.z + off, by2 = Bx.w + off;
    float ltx = fmaxf(ax1, bx1), lty = fmaxf(ay1, by1);
    float rbx = fminf(ax2, bx2), rby = fminf(ay2, by2);
    float ww = fmaxf(rbx - ltx, 0.f), hh = fmaxf(rby - lty, 0.f);
    float inter = ww * hh;
    float a1 = (ax2 - ax1) * (ay2 - ay1);
    float a2 = (bx2 - bx1) * (by2 - by1);
    float iou = __fdiv_rn(inter, a1 + a2 - inter + 1e-9f);
    return iou > 0.5f;
}

// byte-identical box decode for candidate (g, c)
__device__ __forceinline__ float4 decode_box(const float* __restrict__ reg,
                                             const float* __restrict__ props,
                                             int g, int c) {
    float4 p = reinterpret_cast<const float4*>(props)[g];
    float w  = p.z - p.x;
    float h  = p.w - p.y;
    float cx = p.x + 0.5f * w;
    float cy = p.y + 0.5f * h;
    const float4* Q = reinterpret_cast<const float4*>(reg + (size_t)g * (Cn * 4));
    float4 q = Q[c];
    float dx = __fdiv_rn(q.x, 10.0f);
    float dy = __fdiv_rn(q.y, 10.0f);
    float dw = fminf(__fdiv_rn(q.z, 5.0f), CLIPV);
    float dh = fminf(__fdiv_rn(q.w, 5.0f), CLIPV);
    float pcx = dx * w + cx;
    float pcy = dy * h + cy;
    float pw  = expf(dw) * w;
    float ph  = expf(dh) * h;
    float x1 = fminf(fmaxf(pcx - 0.5f * pw, 0.f), 800.f);
    float y1 = fminf(fmaxf(pcy - 0.5f * ph, 0.f), 800.f);
    float x2 = fminf(fmaxf(pcx + 0.5f * pw, 0.f), 800.f);
    float y2 = fminf(fmaxf(pcy + 0.5f * ph, 0.f), 800.f);
    return make_float4(x1, y1, x2, y2);
}

// decode + filter + key emit for one proposal's survivors (warp-wide)
__device__ __forceinline__ void emit_prop(int g, int n, int lane,
                                          unsigned mA, unsigned mB, unsigned mC,
                                          float e0, float e1, float e2, float s,
                                          const float* __restrict__ reg,
                                          const float* __restrict__ props,
                                          bool& ok, float& sc, int& c) {
    int c0  = __popc(mA);
    int c01 = c0 + __popc(mB);
    int tot = c01 + __popc(mC);
    ok = false; sc = 0.f; c = 0;
    if (tot == 0) return;

    int src = 0, k = 0;
    if (lane < c0)       { k = 0; src = __fns(mA, 0, lane + 1); }
    else if (lane < c01) { k = 1; src = __fns(mB, 0, lane - c0 + 1); }
    else if (lane < tot) { k = 2; src = __fns(mC, 0, lane - c01 + 1); }
    src &= 31;
    float eA = __shfl_sync(FULLM, e0, src);
    float eB = __shfl_sync(FULLM, e1, src);
    float eC = __shfl_sync(FULLM, e2, src);
    float e  = (k == 2) ? eC : ((k == 1) ? eB : eA);
    c = src + (k << 5);

    ok = (lane < tot);
    sc = __fdiv_rn(e, s);                 // exact softmax value
    ok = ok && (sc > 0.05f);
    if (ok) {
        float4 bx = decode_box(reg, props, g, c);
        ok = ((bx.z - bx.x) >= 1.0f) && ((bx.w - bx.y) >= 1.0f);
    }
}

// ------------------------------------------------------------------
// K1: two proposals per warp, interleaved chains
// ------------------------------------------------------------------
__global__ __launch_bounds__(256) void k_cand(const float* __restrict__ logits,
                                              const float* __restrict__ reg,
                                              const float* __restrict__ props) {
    int warp = threadIdx.x >> 5;
    int lane = threadIdx.x & 31;
    int gA = blockIdx.x * 16 + warp * 2;      // even
    int gB = gA + 1;                          // same image (8192 | pairs)
    int b  = gA >> 13;
    int nA = gA & (Nn - 1);
    int nB = gB & (Nn - 1);

    const float* LA = logits + (size_t)gA * Cn;
    const float* LB = logits + (size_t)gB * Cn;
    float a0 = LA[lane];
    float b0 = LB[lane];
    float a1 = (lane + 32 < Cn) ? LA[lane + 32] : -1e30f;
    float b1 = (lane + 32 < Cn) ? LB[lane + 32] : -1e30f;
    float a2 = (lane + 64 < Cn) ? LA[lane + 64] : -1e30f;
    float b2 = (lane + 64 < Cn) ? LB[lane + 64] : -1e30f;

    float mxa = fmaxf(a0, fmaxf(a1, a2));
    float mxb = fmaxf(b0, fmaxf(b1, b2));
    #pragma unroll
    for (int o = 16; o; o >>= 1) {
        mxa = fmaxf(mxa, __shfl_xor_sync(FULLM, mxa, o));
        mxb = fmaxf(mxb, __shfl_xor_sync(FULLM, mxb, o));
    }

    float ea0 = expf(a0 - mxa);
    float eb0 = expf(b0 - mxb);
    float ea1 = (lane + 32 < Cn) ? expf(a1 - mxa) : 0.0f;
    float eb1 = (lane + 32 < Cn) ? expf(b1 - mxb) : 0.0f;
    float ea2 = (lane + 64 < Cn) ? expf(a2 - mxa) : 0.0f;
    float eb2 = (lane + 64 < Cn) ? expf(b2 - mxb) : 0.0f;
    float sa = ea0 + ea1 + ea2;
    float sb = eb0 + eb1 + eb2;
    #pragma unroll
    for (int o = 16; o; o >>= 1) {
        sa += __shfl_xor_sync(FULLM, sa, o);
        sb += __shfl_xor_sync(FULLM, sb, o);
    }

    // conservative prefilter (margin >> 1ulp; exact test after compaction)
    float pta = 0.0497f * sa;
    float ptb = 0.0497f * sb;
    bool okA0 = (lane >= 1) && (ea0 > pta);
    bool okA1 = (ea1 > pta);
    bool okA2 = (ea2 > pta);
    bool okB0 = (lane >= 1) && (eb0 > ptb);
    bool okB1 = (eb1 > ptb);
    bool okB2 = (eb2 > ptb);

    unsigned mAa = __ballot_sync(FULLM, okA0);
    unsigned mBa = __ballot_sync(FULLM, okA1);
    unsigned mCa = __ballot_sync(FULLM, okA2);
    unsigned mAb = __ballot_sync(FULLM, okB0);
    unsigned mBb = __ballot_sync(FULLM, okB1);
    unsigned mCb = __ballot_sync(FULLM, okB2);
    if ((mAa | mBa | mCa | mAb | mBb | mCb) == 0u) return;   // warp-uniform

    bool okA, okB; float scA, scB; int cA, cB;
    emit_prop(gA, nA, lane, mAa, mBa, mCa, ea0, ea1, ea2, sa, reg, props, okA, scA, cA);
    emit_prop(gB, nB, lane, mAb, mBb, mCb, eb0, eb1, eb2, sb, reg, props, okB, scB, cB);

    unsigned fmA = __ballot_sync(FULLM, okA);
    unsigned fmB = __ballot_sync(FULLM, okB);
    int cntA = __popc(fmA);
    int tot = cntA + __popc(fmB);
    if (tot) {
        int base = 0;
        if (lane == 0) base = atomicAdd(&g_cnt[b], tot);
        base = __shfl_sync(FULLM, base, 0);
        unsigned below = (1u << lane) - 1u;
        if (okA) {
            int pos = base + __popc(fmA & below);
            if (pos < CAPc) {
                unsigned m = (unsigned)(nA * 90 + (cA - 1));
                unsigned sbb = __float_as_uint(scA);
                g_keys[b][pos] = ((unsigned long long)sbb << 32) | (0xFFFFFFFFu - m);
            }
        }
        if (okB) {
            int pos = base + cntA + __popc(fmB & below);
            if (pos < CAPc) {
                unsigned m = (unsigned)(nB * 90 + (cB - 1));
                unsigned sbb = __float_as_uint(scB);
                g_keys[b][pos] = ((unsigned long long)sbb << 32) | (0xFFFFFFFFu - m);
            }
        }
    }
}

// ------------------------------------------------------------------
// K2 shared memory
// ------------------------------------------------------------------
struct SM {
    float4 sbox[SEL_CAP];               // window boxes (sorted order)
    float4 cls_acc[32][DETS];           // per-warp class accepted scratch
    float4 abox[DETS];                  // global accepted boxes
    unsigned long long skey[SEL_CAP];
    int    slbl[SEL_CAP];
    int    sfx[NB];
    int    chunkcnt[32][128];           // per-(chunk,warp) class counts / bases
    int    cls_rank[SEL_CAP];
    int    cls_list[SEL_CAP];
    int    sflag[SEL_CAP];
    int    cls_cnt[128];
    int    cls_off[96];
    int    albl[DETS];
    int    wtot[32], wexc[32], wsum[32];
    int    s_cnt, s_acc, s_surv;
};

__global__ __launch_bounds__(TPB) void k_nms(const float* __restrict__ reg,
                                             const float* __restrict__ props,
                                             float* __restrict__ out, int out_size) {
    extern __shared__ __align__(16) char smraw[];
    SM* sm = reinterpret_cast<SM*>(smraw);
    int b = blockIdx.x;
    int t = threadIdx.x;
    int lane = t & 31;
    int warp = t >> 5;

    int Ktot = min(g_cnt[b], CAPc);

    // ---- build histogram in smem from keys (MLP-8 batched) ----
    const int PER = NB / TPB;   // 9
    int lo = t * PER;
    #pragma unroll
    for (int i = 0; i < PER; i++) sm->sfx[lo + i] = 0;
    __syncthreads();
    for (int i0 = 0; i0 < Ktot; i0 += TPB * 8) {
        unsigned long long kv[8];
        #pragma unroll
        for (int k = 0; k < 8; k++) {
            int i = i0 + k * TPB + t;
            kv[k] = (i < Ktot) ? g_keys[b][i] : 0ULL;
        }
        #pragma unroll
        for (int k = 0; k < 8; k++) {
            if (kv[k]) {
                int bin = (int)((unsigned)(kv[k] >> 32) >> 12) - BASE_BIN;
                bin = max(0, min(bin, NB - 1));
                atomicAdd(&sm->sfx[bin], 1);
            }
        }
    }
    __syncthreads();

    // ---- hierarchical suffix sums in place ----
    int cnts[PER];
    #pragma unroll
    for (int i = 0; i < PER; i++) cnts[i] = sm->sfx[lo + i];
    int ls = 0;
    #pragma unroll
    for (int i = 0; i < PER; i++) ls += cnts[i];
    int v = ls;
    #pragma unroll
    for (int off = 1; off < 32; off <<= 1) {
        int u = __shfl_down_sync(FULLM, v, off);
        if (lane + off < 32) v += u;
    }
    if (lane == 0) sm->wtot[warp] = v;
    __syncthreads();
    if (t < 32) {
        int x = sm->wtot[t];
        int vv = x;
        #pragma unroll
        for (int off = 1; off < 32; off <<= 1) {
            int u = __shfl_down_sync(FULLM, vv, off);
            if (t + off < 32) vv += u;
        }
        sm->wexc[t] = vv - x;
    }
    if (t == 0) sm->s_acc = 0;
    __syncthreads();
    int run = sm->wexc[warp] + (v - ls);
    for (int i = PER - 1; i >= 0; i--) {
        run += cnts[i];
        sm->sfx[lo + i] = run;
    }
    __syncthreads();

    int b_hi = NB;

    while (sm->s_acc < DETS) {
        int top = (b_hi < NB) ? sm->sfx[b_hi] : 0;
        if (b_hi == 0 || sm->sfx[0] - top == 0) break;

        // smallest wlo with sfx[wlo] - top <= SEL_CAP
        int sl = 0, sh = b_hi;
        while (sl < sh) {
            int mid = (sl + sh) >> 1;
            if (sm->sfx[mid] - top <= SEL_CAP) sh = mid; else sl = mid + 1;
        }
        int wlo = sl;
        if (wlo >= b_hi) wlo = b_hi - 1;
        int whi = b_hi;
        b_hi = wlo;

        if (t == 0) sm->s_cnt = 0;
        __syncthreads();
        // ---- MLP-8 selection scan ----
        for (int i0 = 0; i0 < Ktot; i0 += TPB * 8) {
            unsigned long long kv[8];
            #pragma unroll
            for (int k = 0; k < 8; k++) {
                int i = i0 + k * TPB + t;
                kv[k] = (i < Ktot) ? g_keys[b][i] : 0ULL;
            }
            #pragma unroll
            for (int k = 0; k < 8; k++) {
                if (kv[k]) {
                    int bin = (int)((unsigned)(kv[k] >> 32) >> 12) - BASE_BIN;
                    bin = max(0, min(bin, NB - 1));
                    if (bin >= wlo && bin < whi) {
                        int pos = atomicAdd(&sm->s_cnt, 1);
                        if (pos < SEL_CAP) sm->skey[pos] = kv[k];
                    }
                }
            }
        }
        __syncthreads();
        int nsel = min(sm->s_cnt, SEL_CAP);
        if (nsel == 0) continue;

        {
            int i = nsel + t;
            if (i < SEL_CAP) sm->skey[i] = 0ULL;
        }
        __syncthreads();

        // ---- register+shfl bitonic sort, descending, P=1024 ----
        {
            unsigned long long key = sm->skey[t];
            #pragma unroll
            for (int k2 = 2; k2 <= SEL_CAP; k2 <<= 1) {
                for (int j = k2 >> 1; j > 0; j >>= 1) {
                    unsigned long long partner;
                    if (j >= 32) {
                        __syncthreads();
                        sm->skey[t] = key;
                        __syncthreads();
                        partner = sm->skey[t ^ j];
                    } else {
                        partner = __shfl_xor_sync(FULLM, key, j);
                    }
                    bool desc    = ((t & k2) == 0);
                    bool lowerIx = ((t & j) == 0);
                    bool takeMax = (desc == lowerIx);
                    bool pG      = (partner > key);
                    if (takeMax == pG) key = partner;
                }
            }
            __syncthreads();
            sm->skey[t] = key;
            __syncthreads();
        }

        // ---- decode boxes + labels in sorted order; reset counters ----
        int mylbl;
        if (t < nsel) {
            unsigned m = 0xFFFFFFFFu - (unsigned)sm->skey[t];
            int n = (int)(m / 90u);
            int c = (int)(m % 90u) + 1;
            sm->sbox[t] = decode_box(reg, props, b * Nn + n, c);
            sm->slbl[t] = c;
            mylbl = c;
        } else {
            mylbl = 96 + lane;            // unique-per-lane pad label
        }
        sm->sflag[t] = 0;
        {
            #pragma unroll
            for (int i = 0; i < 4; i++) sm->chunkcnt[(t * 4 + i) >> 7][(t * 4 + i) & 127] = 0;
        }
        __syncthreads();

        // ---- parallel per-chunk ranks: warp w handles items w*32+lane ----
        unsigned peers = __match_any_sync(FULLM, mylbl);
        int lrank = __popc(peers & ((1u << lane) - 1u));
        int leader = __ffs(peers) - 1;
        if (lane == leader) sm->chunkcnt[warp][mylbl] = __popc(peers);
        __syncthreads();

        // ---- per-class prefix across the 32 chunks (128 threads) ----
        if (t < 128) {
            int run2 = 0;
            #pragma unroll 1
            for (int w = 0; w < 32; w++) {
                int tmp = sm->chunkcnt[w][t];
                sm->chunkcnt[w][t] = run2;   // becomes chunk base
                run2 += tmp;
            }
            sm->cls_cnt[t] = run2;
        }
        __syncthreads();

        if (t < nsel) sm->cls_rank[t] = sm->chunkcnt[warp][mylbl] + lrank;
        __syncthreads();

        // ---- exclusive offsets over classes 0..95 ----
        if (t < 32) {
            int c0i = t * 3;
            int s0 = sm->cls_cnt[c0i], s1 = sm->cls_cnt[c0i + 1], s2 = sm->cls_cnt[c0i + 2];
            int tt = s0 + s1 + s2;
            int rn = tt;
            #pragma unroll
            for (int off = 1; off < 32; off <<= 1) {
                int u = __shfl_up_sync(FULLM, rn, off);
                if (lane >= off) rn += u;
            }
            int ex = rn - tt;
            sm->cls_off[c0i] = ex;
            sm->cls_off[c0i + 1] = ex + s0;
            sm->cls_off[c0i + 2] = ex + s0 + s1;
        }
        __syncthreads();

        // ---- scatter per-class lists (stable: score order within class) --
        if (t < nsel) sm->cls_list[sm->cls_off[mylbl] + sm->cls_rank[t]] = t;
        int acc0 = sm->s_acc;
        int quota = DETS - acc0;
        __syncthreads();

        // ---- per-class greedy: warp w handles classes w+1, w+33, w+65 ----
        #pragma unroll
        for (int jc = 0; jc < 3; jc++) {
            int c = warp + 1 + 32 * jc;
            if (c > 90) continue;
            int cnt = sm->cls_cnt[c];
            if (cnt == 0) continue;
            int off = sm->cls_off[c];
            float offv = (float)c * 801.0f;

            int nacc = 0;
            for (int a0 = 0; a0 < acc0; a0 += 32) {
                int a = a0 + lane;
                bool mth = (a < acc0) && (sm->albl[a] == c);
                unsigned mm = __ballot_sync(FULLM, mth);
                if (mth) sm->cls_acc[warp][nacc + __popc(mm & ((1u << lane) - 1u))] = sm->abox[a];
                nacc += __popc(mm);
            }

            int newacc = 0;
            for (int j = 0; j < cnt; j++) {
                int i = sm->cls_list[off + j];
                float4 bx = sm->sbox[i];
                bool sup = false;
                for (int a = lane; a < nacc; a += 32)
                    sup |= iou_sup(sm->cls_acc[warp][a], bx, offv);
                if (!__any_sync(FULLM, sup)) {
                    if (lane == 0) {
                        sm->sflag[i] = 1;
                        sm->cls_acc[warp][nacc] = bx;
                    }
                    nacc++;
                    newacc++;
                    if (newacc >= quota) break;
                }
            }
        }
        __syncthreads();

        // ---- prefix over survivor flags; output first quota in order ----
        {
            int f = sm->sflag[t];
            int scn = f;
            #pragma unroll
            for (int off = 1; off < 32; off <<= 1) {
                int u = __shfl_up_sync(FULLM, scn, off);
                if (lane >= off) scn += u;
            }
            if (lane == 31) sm->wsum[warp] = scn;
            __syncthreads();
            if (t < 32) {
                int x = sm->wsum[t];
                int s2 = x;
                #pragma unroll
                for (int off = 1; off < 32; off <<= 1) {
                    int u = __shfl_up_sync(FULLM, s2, off);
                    if (t >= off) s2 += u;
                }
                sm->wsum[t] = s2 - x;
            }
            __syncthreads();
            int incl = scn + sm->wsum[warp];
            int r = incl - f;
            if (f && (acc0 + r) < DETS) {
                int slot = acc0 + r;
                float4 bx = sm->sbox[t];
                int lbl = sm->slbl[t];
                sm->abox[slot] = bx;
                sm->albl[slot] = lbl;
                float sc = __uint_as_float((unsigned)(sm->skey[t] >> 32));
                stf(out, b * (DETS * 4) + slot * 4 + 0, bx.x, out_size);
                stf(out, b * (DETS * 4) + slot * 4 + 1, bx.y, out_size);
                stf(out, b * (DETS * 4) + slot * 4 + 2, bx.z, out_size);
                stf(out, b * (DETS * 4) + slot * 4 + 3, bx.w, out_size);
                stf(out, Bn * DETS * 4 + b * DETS + slot, sc, out_size);
                stf(out, Bn * DETS * 5 + b * DETS + slot, (float)lbl, out_size);
                stf(out, Bn * DETS * 6 + b * DETS + slot, 1.0f, out_size);
            }
            if (t == TPB - 1) sm->s_surv = incl;
            __syncthreads();
            if (t == 0) sm->s_acc = min(acc0 + sm->s_surv, DETS);
            __syncthreads();
        }
    }

    // ---- zero-fill remaining detection slots ----
    __syncthreads();
    int accF = sm->s_acc;
    for (int a = accF + t; a < DETS; a += TPB) {
        stf(out, b * (DETS * 4) + a * 4 + 0, 0.f, out_size);
        stf(out, b * (DETS * 4) + a * 4 + 1, 0.f, out_size);
        stf(out, b * (DETS * 4) + a * 4 + 2, 0.f, out_size);
        stf(out, b * (DETS * 4) + a * 4 + 3, 0.f, out_size);
        stf(out, Bn * DETS * 4 + b * DETS + a, 0.f, out_size);
        stf(out, Bn * DETS * 5 + b * DETS + a, 0.f, out_size);
        stf(out, Bn * DETS * 6 + b * DETS + a, 0.f, out_size);
    }

    // ---- restore zeros for next graph replay ----
    if (t == 0) g_cnt[b] = 0;
}

// ------------------------------------------------------------------
// launcher
// ------------------------------------------------------------------
extern "C" void kernel_launch(void* const* d_in, const int* in_sizes, int n_in,
                              void* d_out, int out_size) {
    const float* logits = nullptr;
    const float* reg    = nullptr;
    const float* props  = nullptr;
    for (int i = 0; i < n_in; i++) {
        if      (in_sizes[i] == Bn * Nn * Cn)     logits = (const float*)d_in[i];
        else if (in_sizes[i] == Bn * Nn * Cn * 4) reg    = (const float*)d_in[i];
        else if (in_sizes[i] == Bn * Nn * 4)      props  = (const float*)d_in[i];
    }
    if (!logits && n_in > 0) logits = (const float*)d_in[0];
    if (!reg    && n_in > 1) reg    = (const float*)d_in[1];
    if (!props  && n_in > 2) props  = (const float*)d_in[2];

    cudaFuncSetAttribute(k_nms, cudaFuncAttributeMaxDynamicSharedMemorySize,
                         (int)sizeof(SM));

    k_cand<<<(Bn * Nn) / 16, 256>>>(logits, reg, props);
    k_nms<<<Bn, TPB, sizeof(SM)>>>(reg, props, (float*)d_out, out_size);
}